// round 3
// baseline (speedup 1.0000x reference)
#include <cuda_runtime.h>
#include <math.h>

#define N_NODES 50000
#define N_EDGES 1600000
#define IN_DIM 128
#define HID 64
#define EPS 1e-6f

// ---------------- scratch (device globals; no allocation allowed) ----------------
__device__ int   g_cnt[N_NODES];
__device__ int   g_fill[N_NODES];
__device__ int   g_indptr[N_NODES + 1];
__device__ float g_invdeg[N_NODES];
__device__ int   g_srcsort[N_EDGES];
__device__ float g_m[N_NODES * HID];
__device__ float g_s[N_NODES * HID];
__device__ float g_hA[N_NODES * HID];
__device__ float g_hB[N_NODES * HID];

// ---------------- CSR build ----------------
__global__ void k_zero() {
    int i = blockIdx.x * blockDim.x + threadIdx.x;
    if (i < N_NODES) { g_cnt[i] = 0; g_fill[i] = 0; }
}

__global__ void k_count(const int* __restrict__ ei) {
    int e = blockIdx.x * blockDim.x + threadIdx.x;
    if (e < N_EDGES) {
        int d = ei[N_EDGES + e];
        atomicAdd(&g_cnt[d], 1);
    }
}

// single-block exclusive scan over g_cnt -> g_indptr, also writes inv_deg
__global__ void k_scan() {
    __shared__ int wsum[32];
    int tid = threadIdx.x;
    int lane = tid & 31, wid = tid >> 5;
    int carry = 0;
    if (tid == 0) g_indptr[0] = 0;
    for (int base = 0; base < N_NODES; base += 1024) {
        int i = base + tid;
        int v = (i < N_NODES) ? g_cnt[i] : 0;
        int x = v;
        #pragma unroll
        for (int o = 1; o < 32; o <<= 1) {
            int y = __shfl_up_sync(0xffffffffu, x, o);
            if (lane >= o) x += y;
        }
        if (lane == 31) wsum[wid] = x;
        __syncthreads();
        if (wid == 0) {
            int w = wsum[lane];
            #pragma unroll
            for (int o = 1; o < 32; o <<= 1) {
                int y = __shfl_up_sync(0xffffffffu, w, o);
                if (lane >= o) w += y;
            }
            wsum[lane] = w;
        }
        __syncthreads();
        int pre = (wid > 0) ? wsum[wid - 1] : 0;
        int incl = carry + pre + x;
        if (i < N_NODES) {
            g_indptr[i + 1] = incl;
            g_invdeg[i] = 1.0f / fmaxf((float)v, 1.0f);
        }
        carry += wsum[31];
        __syncthreads();
    }
}

__global__ void k_scatter(const int* __restrict__ ei) {
    int e = blockIdx.x * blockDim.x + threadIdx.x;
    if (e < N_EDGES) {
        int d = ei[N_EDGES + e];
        int s = ei[e];
        int pos = g_indptr[d] + atomicAdd(&g_fill[d], 1);
        g_srcsort[pos] = s;
    }
}

// ---------------- fused dual GEMM: m = h@wn, s = h@ws ----------------
// block = 256 threads, tile = 32 rows x 128 cols (cols 0..63 -> m, 64..127 -> s)
template <int K>
__global__ void __launch_bounds__(256) k_gemm(const float* __restrict__ h,
                                              const float* __restrict__ wn,
                                              const float* __restrict__ ws,
                                              float* __restrict__ mo,
                                              float* __restrict__ so) {
    __shared__ float hs[32][33];     // [k][row], padded
    __shared__ float wsm[32][128];   // [k][col]
    int tid = threadIdx.x;
    int row0 = blockIdx.x * 32;
    int tr = (tid >> 5) * 4;         // 0..28 (rows)
    int tc = (tid & 31) * 4;         // 0..124 (cols)
    float acc[4][4];
    #pragma unroll
    for (int i = 0; i < 4; i++)
        #pragma unroll
        for (int j = 0; j < 4; j++) acc[i][j] = 0.f;

    for (int kb = 0; kb < K; kb += 32) {
        int rr0 = tid >> 5, kk = tid & 31;
        #pragma unroll
        for (int i = 0; i < 4; i++) {
            int r = rr0 + i * 8;
            int grow = row0 + r;
            hs[kk][r] = (grow < N_NODES) ? h[(size_t)grow * K + kb + kk] : 0.f;
        }
        #pragma unroll
        for (int i = 0; i < 16; i++) {
            int lin = tid + i * 256;
            int k = lin >> 7, c = lin & 127;
            wsm[k][c] = (c < 64) ? wn[(kb + k) * 64 + c] : ws[(kb + k) * 64 + (c - 64)];
        }
        __syncthreads();
        #pragma unroll
        for (int k = 0; k < 32; k++) {
            float4 wv = *(const float4*)&wsm[k][tc];
            float h0 = hs[k][tr], h1 = hs[k][tr + 1], h2 = hs[k][tr + 2], h3 = hs[k][tr + 3];
            acc[0][0] = fmaf(h0, wv.x, acc[0][0]);
            acc[0][1] = fmaf(h0, wv.y, acc[0][1]);
            acc[0][2] = fmaf(h0, wv.z, acc[0][2]);
            acc[0][3] = fmaf(h0, wv.w, acc[0][3]);
            acc[1][0] = fmaf(h1, wv.x, acc[1][0]);
            acc[1][1] = fmaf(h1, wv.y, acc[1][1]);
            acc[1][2] = fmaf(h1, wv.z, acc[1][2]);
            acc[1][3] = fmaf(h1, wv.w, acc[1][3]);
            acc[2][0] = fmaf(h2, wv.x, acc[2][0]);
            acc[2][1] = fmaf(h2, wv.y, acc[2][1]);
            acc[2][2] = fmaf(h2, wv.z, acc[2][2]);
            acc[2][3] = fmaf(h2, wv.w, acc[2][3]);
            acc[3][0] = fmaf(h3, wv.x, acc[3][0]);
            acc[3][1] = fmaf(h3, wv.y, acc[3][1]);
            acc[3][2] = fmaf(h3, wv.z, acc[3][2]);
            acc[3][3] = fmaf(h3, wv.w, acc[3][3]);
        }
        __syncthreads();
    }
    #pragma unroll
    for (int i = 0; i < 4; i++) {
        int grow = row0 + tr + i;
        if (grow < N_NODES) {
            float4 v = make_float4(acc[i][0], acc[i][1], acc[i][2], acc[i][3]);
            if (tc < 64) *(float4*)(mo + (size_t)grow * 64 + tc) = v;
            else         *(float4*)(so + (size_t)grow * 64 + (tc - 64)) = v;
        }
    }
}

// ---------------- fused aggregate + relu + projective normalize ----------------
// one warp per node; lane holds channels [2*lane, 2*lane+1]
__global__ void k_agg(const float* __restrict__ m, const float* __restrict__ s,
                      float* __restrict__ hout) {
    int gw = (blockIdx.x * blockDim.x + threadIdx.x) >> 5;
    int lane = threadIdx.x & 31;
    if (gw >= N_NODES) return;
    int beg = g_indptr[gw], end = g_indptr[gw + 1];
    float a0 = 0.f, a1 = 0.f, b0 = 0.f, b1 = 0.f, c0 = 0.f, c1 = 0.f, d0 = 0.f, d1 = 0.f;
    int e = beg;
    for (; e + 4 <= end; e += 4) {
        int s0 = g_srcsort[e], s1 = g_srcsort[e + 1], s2 = g_srcsort[e + 2], s3 = g_srcsort[e + 3];
        float2 v0 = *(const float2*)(m + (size_t)s0 * HID + lane * 2);
        float2 v1 = *(const float2*)(m + (size_t)s1 * HID + lane * 2);
        float2 v2 = *(const float2*)(m + (size_t)s2 * HID + lane * 2);
        float2 v3 = *(const float2*)(m + (size_t)s3 * HID + lane * 2);
        a0 += v0.x; a1 += v0.y;
        b0 += v1.x; b1 += v1.y;
        c0 += v2.x; c1 += v2.y;
        d0 += v3.x; d1 += v3.y;
    }
    for (; e < end; e++) {
        int s0 = g_srcsort[e];
        float2 v0 = *(const float2*)(m + (size_t)s0 * HID + lane * 2);
        a0 += v0.x; a1 += v0.y;
    }
    a0 += b0 + c0 + d0;
    a1 += b1 + c1 + d1;
    float idg = g_invdeg[gw];
    float2 sv = *(const float2*)(s + (size_t)gw * HID + lane * 2);
    float h0 = fmaxf(fmaf(a0, idg, sv.x), 0.f);
    float h1 = fmaxf(fmaf(a1, idg, sv.y), 0.f);
    float ss = h0 * h0 + h1 * h1;
    #pragma unroll
    for (int o = 16; o; o >>= 1) ss += __shfl_xor_sync(0xffffffffu, ss, o);
    float inv = 1.0f / (sqrtf(ss) + EPS);
    float2 o2;
    o2.x = h0 * inv;
    o2.y = h1 * inv;
    *(float2*)(hout + (size_t)gw * HID + lane * 2) = o2;
}

// ---------------- MLP head: sigmoid(relu(h@mw1+mb1)@mw2+mb2) ----------------
__global__ void k_mlp(const float* __restrict__ h, const float* __restrict__ mw1,
                      const float* __restrict__ mb1, const float* __restrict__ mw2,
                      const float* __restrict__ mb2, float* __restrict__ out) {
    __shared__ float w1[64 * 32];
    __shared__ float b1[32];
    __shared__ float w2[32];
    for (int i = threadIdx.x; i < 64 * 32; i += blockDim.x) w1[i] = mw1[i];
    if (threadIdx.x < 32) {
        b1[threadIdx.x] = mb1[threadIdx.x];
        w2[threadIdx.x] = mw2[threadIdx.x];
    }
    __syncthreads();
    int gw = (blockIdx.x * blockDim.x + threadIdx.x) >> 5;
    int lane = threadIdx.x & 31;
    if (gw >= N_NODES) return;
    float2 hv = *(const float2*)(h + (size_t)gw * HID + lane * 2);
    float acc = b1[lane];
    #pragma unroll
    for (int k = 0; k < 64; k++) {
        float hk = __shfl_sync(0xffffffffu, (k & 1) ? hv.y : hv.x, k >> 1);
        acc = fmaf(hk, w1[k * 32 + lane], acc);
    }
    acc = fmaxf(acc, 0.f);
    float z = acc * w2[lane];
    #pragma unroll
    for (int o = 16; o; o >>= 1) z += __shfl_xor_sync(0xffffffffu, z, o);
    if (lane == 0) out[gw] = 1.0f / (1.0f + expf(-(z + mb2[0])));
}

// ---------------- host ----------------
extern "C" void kernel_launch(void* const* d_in, const int* in_sizes, int n_in,
                              void* d_out, int out_size) {
    const float* x   = (const float*)d_in[0];
    const int*   ei  = (const int*)d_in[1];   // int32! (JAX default x64-disabled)
    const float* w0s = (const float*)d_in[2];
    const float* w0n = (const float*)d_in[3];
    const float* w1s = (const float*)d_in[4];
    const float* w1n = (const float*)d_in[5];
    const float* w2s = (const float*)d_in[6];
    const float* w2n = (const float*)d_in[7];
    const float* mw1 = (const float*)d_in[8];
    const float* mb1 = (const float*)d_in[9];
    const float* mw2 = (const float*)d_in[10];
    const float* mb2 = (const float*)d_in[11];
    float*       out = (float*)d_out;

    float *pm, *ps, *phA, *phB;
    cudaGetSymbolAddress((void**)&pm,  g_m);
    cudaGetSymbolAddress((void**)&ps,  g_s);
    cudaGetSymbolAddress((void**)&phA, g_hA);
    cudaGetSymbolAddress((void**)&phB, g_hB);

    const int EB = (N_EDGES + 255) / 256;
    const int NB = (N_NODES + 255) / 256;
    const int GB = (N_NODES + 31) / 32;         // gemm blocks (32 rows each)
    const int WB = (N_NODES * 32 + 255) / 256;  // warp-per-node blocks

    // CSR build
    k_zero<<<NB, 256>>>();
    k_count<<<EB, 256>>>(ei);
    k_scan<<<1, 1024>>>();
    k_scatter<<<EB, 256>>>(ei);

    // layer 0 (K = 128)
    k_gemm<IN_DIM><<<GB, 256>>>(x, w0n, w0s, pm, ps);
    k_agg<<<WB, 256>>>(pm, ps, phA);
    // layer 1 (K = 64)
    k_gemm<HID><<<GB, 256>>>(phA, w1n, w1s, pm, ps);
    k_agg<<<WB, 256>>>(pm, ps, phB);
    // layer 2 (K = 64)
    k_gemm<HID><<<GB, 256>>>(phB, w2n, w2s, pm, ps);
    k_agg<<<WB, 256>>>(pm, ps, phA);

    // MLP head
    k_mlp<<<WB, 256>>>(phA, mw1, mb1, mw2, mb2, out);
}